// round 2
// baseline (speedup 1.0000x reference)
#include <cuda_runtime.h>
#include <math.h>

#define Bn 16
#define Nn 25000
#define Mn 64
#define TILE 256
#define NB 24
#define NBLOCKS (NB*Bn)

// ---- scratch (no allocations allowed) ----
__device__ float g_piou[Bn*Mn*NB];
__device__ int   g_pidx[Bn*Mn*NB];
__device__ float g_fpart[NBLOCKS];
__device__ unsigned int g_ctr = 0;

__global__ __launch_bounds__(256) void k_all(const float* __restrict__ preds,
                                             const float* __restrict__ targets,
                                             float* __restrict__ out) {
    const int b    = blockIdx.y;
    const int bx   = blockIdx.x;
    const int tid  = threadIdx.x;
    const int lane = tid & 31;
    const int warp = tid >> 5;

    // main-phase shared
    __shared__ float4 s_box[TILE];
    __shared__ float  s_area[TILE];
    __shared__ float  s_red[256];
    __shared__ float  s_miou[8*Mn];
    __shared__ int    s_midx[8*Mn];
    // tail-phase shared
    __shared__ float  s_biou[Bn*Mn];
    __shared__ int    s_bidx[Bn*Mn];
    __shared__ float  s_ci[Bn*Mn];
    __shared__ float  s_fd[Bn*Mn];
    __shared__ unsigned char s_okv[Bn*Mn];
    __shared__ float  s_focal[Bn];
    __shared__ int    s_last;

    // ---- phase 1: per-warp IoU argmax over this block's pred stripe ----
    const float4 t0 = __ldg((const float4*)targets + (b*Mn + lane));
    const float4 t1 = __ldg((const float4*)targets + (b*Mn + lane + 32));
    const float ta0 = (t0.z - t0.x) * (t0.w - t0.y);
    const float ta1 = (t1.z - t1.x) * (t1.w - t1.y);

    float best0 = -1e30f, best1 = -1e30f;
    int   bi0 = Nn, bi1 = Nn;
    float facc = 0.f;

    const float* pb = preds + (size_t)b * Nn * 5;

    for (int base = bx * TILE; base < Nn; base += NB * TILE) {
        const int cnt = min(TILE, Nn - base);
        __syncthreads();   // previous tile fully consumed
        {
            float x1, y1, x2, y2, area;
            if (tid < cnt) {
                const float* pr = pb + (size_t)(base + tid) * 5;
                float cx = pr[0], cy = pr[1];
                float w = fmaxf(pr[2], 1e-4f), h = fmaxf(pr[3], 1e-4f);
                float conf = pr[4];
                x1 = cx - 0.5f * w; x2 = cx + 0.5f * w;
                y1 = cy - 0.5f * h; y2 = cy + 0.5f * h;
                area = (x2 - x1) * (y2 - y1);
                // focal loss, target = 0 (exact reference formula)
                float p  = 1.f / (1.f + expf(-conf));
                float ce = fmaxf(conf, 0.f) + log1pf(expf(-fabsf(conf)));
                float pt = fminf(fmaxf(1.f - p, 1e-6f), 1.f - 1e-6f);
                float om = 1.f - pt;
                facc += 0.75f * om * om * ce;
            } else {
                // pad: degenerate far-away box -> iou exactly 0, never wins strict >
                x1 = y1 = x2 = y2 = -3e8f; area = 0.f;
            }
            s_box[tid]  = make_float4(x1, y1, x2, y2);
            s_area[tid] = area;
        }
        __syncthreads();

        const int pbase = base + warp * 32;
        #pragma unroll 8
        for (int k = 0; k < 32; k++) {
            const float4 bx4 = s_box[warp * 32 + k];   // broadcast LDS
            const float  ar  = s_area[warp * 32 + k];
            const int    cid = pbase + k;
            {
                float iw = fmaxf(fminf(bx4.z, t0.z) - fmaxf(bx4.x, t0.x), 0.f);
                float ih = fmaxf(fminf(bx4.w, t0.w) - fmaxf(bx4.y, t0.y), 0.f);
                float inter = iw * ih;
                float iou = __fdividef(inter, ar + ta0 - inter);
                if (iou > best0) { best0 = iou; bi0 = cid; }
            }
            {
                float iw = fmaxf(fminf(bx4.z, t1.z) - fmaxf(bx4.x, t1.x), 0.f);
                float ih = fmaxf(fminf(bx4.w, t1.w) - fmaxf(bx4.y, t1.y), 0.f);
                float inter = iw * ih;
                float iou = __fdividef(inter, ar + ta1 - inter);
                if (iou > best1) { best1 = iou; bi1 = cid; }
            }
        }
    }

    // ---- phase 2: intra-block merge (8 warps -> 1 partial per (b,m)) ----
    s_miou[warp*Mn + lane]      = best0;  s_midx[warp*Mn + lane]      = bi0;
    s_miou[warp*Mn + lane + 32] = best1;  s_midx[warp*Mn + lane + 32] = bi1;
    s_red[tid] = facc;
    __syncthreads();

    for (int s = 128; s > 0; s >>= 1) {
        if (tid < s) s_red[tid] += s_red[tid + s];
        __syncthreads();
    }

    if (tid < Mn) {
        float bv = -1e30f; int bi = 0x7fffffff;
        #pragma unroll
        for (int w = 0; w < 8; w++) {
            float v = s_miou[w*Mn + tid]; int id = s_midx[w*Mn + tid];
            if (v > bv || (v == bv && id < bi)) { bv = v; bi = id; }
        }
        g_piou[(b*Mn + tid)*NB + bx] = bv;
        g_pidx[(b*Mn + tid)*NB + bx] = bi;
    }
    if (tid == 0) g_fpart[b*NB + bx] = s_red[0];

    // ---- phase 3: last block does the tail ----
    __threadfence();
    if (tid == 0) {
        unsigned int old = atomicAdd(&g_ctr, 1u);
        s_last = (old == NBLOCKS - 1) ? 1 : 0;
    }
    __syncthreads();
    if (!s_last) return;
    __threadfence();

    // 3a) merge NB partials per (b,m)
    #pragma unroll
    for (int i = 0; i < 4; i++) {
        const int p = tid + i * 256;               // p = b*Mn + m
        const float* pi = g_piou + p * NB;
        const int*   px = g_pidx + p * NB;
        float bv = -1e30f; int bi = 0x7fffffff;
        #pragma unroll
        for (int j = 0; j < NB; j++) {
            float v = pi[j]; int id = px[j];
            if (v > bv || (v == bv && id < bi)) { bv = v; bi = id; }
        }
        s_biou[p] = bv; s_bidx[p] = bi;
    }
    if (tid < Bn) {
        float s = 0.f;
        #pragma unroll
        for (int j = 0; j < NB; j++) s += g_fpart[tid*NB + j];
        s_focal[tid] = s;
    }
    __syncthreads();

    // 3b) greedy dedup (closed form) + CIoU + focal correction
    #pragma unroll
    for (int i = 0; i < 4; i++) {
        const int p  = tid + i * 256;
        const int b2 = p >> 6;
        const int m  = p & 63;
        const float iou_b = s_biou[p];
        const int   idx   = s_bidx[p];

        bool ok = iou_b > 0.2f;
        if (ok) {
            for (int mp = 0; mp < m; mp++)
                if (s_bidx[(b2<<6) + mp] == idx && s_biou[(b2<<6) + mp] > 0.2f) { ok = false; break; }
        }

        float ci = 0.f, fd = 0.f;
        if (ok) {
            const float* pr = preds + ((size_t)b2*Nn + idx) * 5;
            float cx = pr[0], cy = pr[1];
            float w = fmaxf(pr[2], 1e-4f), h = fmaxf(pr[3], 1e-4f);
            float conf = pr[4];
            float x1p = cx - 0.5f*w, x2p = cx + 0.5f*w;
            float y1p = cy - 0.5f*h, y2p = cy + 0.5f*h;
            float4 t = __ldg((const float4*)targets + p);
            float x1t = t.x, y1t = t.y, x2t = t.z, y2t = t.w;

            float inter = fmaxf(fminf(x2p,x2t) - fmaxf(x1p,x1t), 0.f)
                        * fmaxf(fminf(y2p,y2t) - fmaxf(y1p,y1t), 0.f);
            float un  = (x2p-x1p)*(y2p-y1p) + (x2t-x1t)*(y2t-y1t) - inter;
            float iou = inter / (un + 1e-7f);
            float cw = fmaxf(x2p,x2t) - fminf(x1p,x1t);
            float ch = fmaxf(y2p,y2t) - fminf(y1p,y1t);
            float diag = cw*cw + ch*ch + 1e-7f;
            float dx = x1p + x2p - x1t - x2t;
            float dy = y1p + y2p - y1t - y2t;
            float centers = (dx*dx + dy*dy) * 0.25f;
            float wp = x2p - x1p, hp = y2p - y1p;
            float wt = x2t - x1t, ht = y2t - y1t;
            float dv = atanf(wt/ht) - atanf(wp/hp);
            float v  = (float)(4.0/(M_PI*M_PI)) * dv * dv;
            float alpha = v / (1.f - iou + v + 1e-7f);
            ci = 1.f - iou + centers/diag + alpha*v;

            // focal(target=1) - focal(target=0) correction for this pred
            float pp  = 1.f / (1.f + expf(-conf));
            float l1e = log1pf(expf(-fabsf(conf)));
            float ce1 = fmaxf(conf, 0.f) - conf + l1e;
            float ce0 = fmaxf(conf, 0.f) + l1e;
            float pt1 = fminf(fmaxf(pp,       1e-6f), 1.f - 1e-6f);
            float pt0 = fminf(fmaxf(1.f - pp, 1e-6f), 1.f - 1e-6f);
            float a1 = 1.f - pt1, a0 = 1.f - pt0;
            fd = 0.25f*a1*a1*ce1 - 0.75f*a0*a0*ce0;
        }
        s_ci[p] = ci; s_fd[p] = fd; s_okv[p] = ok ? 1 : 0;
    }
    __syncthreads();

    // 3c) per-image loss, final mean
    if (tid < Bn) {
        float sc = 0.f, sf = 0.f; int n = 0;
        #pragma unroll
        for (int m = 0; m < Mn; m++) {
            sc += s_ci[(tid<<6) + m];
            sf += s_fd[(tid<<6) + m];
            n  += s_okv[(tid<<6) + m];
        }
        float conf_loss = (s_focal[tid] + sf) / (float)Nn;
        float box = (n > 0) ? sc / (float)n : 0.f;
        s_red[tid] = conf_loss + box;
    }
    __syncthreads();
    if (tid == 0) {
        float s = 0.f;
        #pragma unroll
        for (int i = 0; i < Bn; i++) s += s_red[i];
        out[0] = s * (1.f / (float)Bn);
        g_ctr = 0;   // reset for next graph replay
    }
}

extern "C" void kernel_launch(void* const* d_in, const int* in_sizes, int n_in,
                              void* d_out, int out_size) {
    const float* preds   = (const float*)d_in[0];
    const float* targets = (const float*)d_in[1];
    float* out = (float*)d_out;
    k_all<<<dim3(NB, Bn), 256>>>(preds, targets, out);
}

// round 3
// speedup vs baseline: 1.9898x; 1.9898x over previous
#include <cuda_runtime.h>
#include <math.h>

#define Bn 16
#define Nn 25000
#define Mn 64
#define TILE 256
#define NTILES ((Nn + TILE - 1) / TILE)   // 98

// ---- scratch (no allocations allowed) ----
__device__ unsigned long long g_pack[Bn*Mn];   // (iou_bits<<32) | ~idx
__device__ float g_focal[Bn];

__global__ void k_init() {
    int t = blockIdx.x * blockDim.x + threadIdx.x;
    if (t < Bn*Mn) g_pack[t] = 0ull;
    if (t < Bn)    g_focal[t] = 0.f;
}

// One 256-pred tile per block. Lane l of each warp owns targets l and l+32 in
// registers; each warp streams its 32 preds of the tile via broadcast LDS.
__global__ __launch_bounds__(256) void k_main(const float* __restrict__ preds,
                                              const float* __restrict__ targets) {
    const int b    = blockIdx.y;
    const int base = blockIdx.x * TILE;
    const int tid  = threadIdx.x;
    const int lane = tid & 31;
    const int warp = tid >> 5;

    __shared__ float4 s_box[TILE];
    __shared__ float  s_area[TILE];
    __shared__ unsigned long long s_m[8*Mn];
    __shared__ float  s_red[8];

    const float4 t0 = __ldg((const float4*)targets + (b*Mn + lane));
    const float4 t1 = __ldg((const float4*)targets + (b*Mn + lane + 32));
    const float ta0 = (t0.z - t0.x) * (t0.w - t0.y);
    const float ta1 = (t1.z - t1.x) * (t1.w - t1.y);

    const int cnt = min(TILE, Nn - base);
    float facc = 0.f;
    {
        // stage + convert + focal(target=0): one pred per thread
        float x1, y1, x2, y2, area;
        if (tid < cnt) {
            const float* pr = preds + ((size_t)b * Nn + base + tid) * 5;
            float cx = pr[0], cy = pr[1];
            float w = fmaxf(pr[2], 1e-4f), h = fmaxf(pr[3], 1e-4f);
            float conf = pr[4];
            x1 = cx - 0.5f * w; x2 = cx + 0.5f * w;
            y1 = cy - 0.5f * h; y2 = cy + 0.5f * h;
            area = (x2 - x1) * (y2 - y1);
            float p  = 1.f / (1.f + expf(-conf));
            float ce = fmaxf(conf, 0.f) + log1pf(expf(-fabsf(conf)));
            float pt = fminf(fmaxf(1.f - p, 1e-6f), 1.f - 1e-6f);
            float om = 1.f - pt;
            facc = 0.75f * om * om * ce;
        } else {
            // pad: degenerate far box -> iou exactly 0; larger idx loses ties
            x1 = y1 = x2 = y2 = -3e8f; area = 0.f;
        }
        s_box[tid]  = make_float4(x1, y1, x2, y2);
        s_area[tid] = area;
    }
    __syncthreads();

    float best0 = -1e30f, best1 = -1e30f;
    int   bi0 = 0, bi1 = 0;
    const int pbase = base + warp * 32;

    #pragma unroll 8
    for (int k = 0; k < 32; k++) {
        const float4 bx = s_box[warp * 32 + k];   // broadcast LDS
        const float  ar = s_area[warp * 32 + k];
        {
            float iw = fmaxf(fminf(bx.z, t0.z) - fmaxf(bx.x, t0.x), 0.f);
            float ih = fmaxf(fminf(bx.w, t0.w) - fmaxf(bx.y, t0.y), 0.f);
            float inter = iw * ih;
            float iou = __fdividef(inter, ar + ta0 - inter);
            if (iou > best0) { best0 = iou; bi0 = pbase + k; }
        }
        {
            float iw = fmaxf(fminf(bx.z, t1.z) - fmaxf(bx.x, t1.x), 0.f);
            float ih = fmaxf(fminf(bx.w, t1.w) - fmaxf(bx.y, t1.y), 0.f);
            float inter = iw * ih;
            float iou = __fdividef(inter, ar + ta1 - inter);
            if (iou > best1) { best1 = iou; bi1 = pbase + k; }
        }
    }

    // pack: higher iou wins; on iou tie, ~idx makes SMALLER idx win
    s_m[warp*Mn + lane] =
        ((unsigned long long)__float_as_uint(best0) << 32) | (unsigned)(~bi0);
    s_m[warp*Mn + lane + 32] =
        ((unsigned long long)__float_as_uint(best1) << 32) | (unsigned)(~bi1);

    // focal warp-reduce
    #pragma unroll
    for (int off = 16; off; off >>= 1)
        facc += __shfl_xor_sync(0xffffffffu, facc, off);
    if (lane == 0) s_red[warp] = facc;
    __syncthreads();

    if (tid < Mn) {
        unsigned long long bv = 0ull;
        #pragma unroll
        for (int w = 0; w < 8; w++) {
            unsigned long long v = s_m[w*Mn + tid];
            if (v > bv) bv = v;
        }
        atomicMax(&g_pack[b*Mn + tid], bv);
    }
    if (tid == 64) {
        float s = 0.f;
        #pragma unroll
        for (int w = 0; w < 8; w++) s += s_red[w];
        atomicAdd(&g_focal[b], s);
    }
}

// Single block: greedy dedup (closed form), CIoU, focal corrections, final mean.
__global__ __launch_bounds__(1024) void k_final(const float* __restrict__ preds,
                                                const float* __restrict__ targets,
                                                float* __restrict__ out) {
    const int tid = threadIdx.x;          // tid = b*64 + m
    const int b = tid >> 6, m = tid & 63;

    __shared__ float s_iou[Bn*Mn];
    __shared__ int   s_idx[Bn*Mn];
    __shared__ float s_ci[Bn*Mn], s_fd[Bn*Mn];
    __shared__ unsigned char s_ok[Bn*Mn];
    __shared__ float s_per[Bn];

    unsigned long long v = g_pack[tid];
    float iou_b = __uint_as_float((unsigned)(v >> 32));
    int   idx   = (int)(~(unsigned)v);
    s_iou[tid] = iou_b;
    s_idx[tid] = idx;
    __syncthreads();

    bool ok = iou_b > 0.2f;
    if (ok) {
        for (int mp = 0; mp < m; mp++)
            if (s_idx[(b<<6) + mp] == idx && s_iou[(b<<6) + mp] > 0.2f) { ok = false; break; }
    }

    float ci = 0.f, fd = 0.f;
    if (ok) {
        const float* pr = preds + ((size_t)b*Nn + idx) * 5;
        float cx = pr[0], cy = pr[1];
        float w = fmaxf(pr[2], 1e-4f), h = fmaxf(pr[3], 1e-4f);
        float conf = pr[4];
        float x1p = cx - 0.5f*w, x2p = cx + 0.5f*w;
        float y1p = cy - 0.5f*h, y2p = cy + 0.5f*h;
        float4 t = __ldg((const float4*)targets + tid);
        float x1t = t.x, y1t = t.y, x2t = t.z, y2t = t.w;

        float inter = fmaxf(fminf(x2p,x2t) - fmaxf(x1p,x1t), 0.f)
                    * fmaxf(fminf(y2p,y2t) - fmaxf(y1p,y1t), 0.f);
        float un  = (x2p-x1p)*(y2p-y1p) + (x2t-x1t)*(y2t-y1t) - inter;
        float iou = inter / (un + 1e-7f);
        float cw = fmaxf(x2p,x2t) - fminf(x1p,x1t);
        float ch = fmaxf(y2p,y2t) - fminf(y1p,y1t);
        float diag = cw*cw + ch*ch + 1e-7f;
        float dx = x1p + x2p - x1t - x2t;
        float dy = y1p + y2p - y1t - y2t;
        float centers = (dx*dx + dy*dy) * 0.25f;
        float wp = x2p - x1p, hp = y2p - y1p;
        float wt = x2t - x1t, ht = y2t - y1t;
        float dv = atanf(wt/ht) - atanf(wp/hp);
        float vv = (float)(4.0/(M_PI*M_PI)) * dv * dv;
        float alpha = vv / (1.f - iou + vv + 1e-7f);
        ci = 1.f - iou + centers/diag + alpha*vv;

        // focal(target=1) - focal(target=0) correction for this pred
        float pp  = 1.f / (1.f + expf(-conf));
        float l1e = log1pf(expf(-fabsf(conf)));
        float ce1 = fmaxf(conf, 0.f) - conf + l1e;
        float ce0 = fmaxf(conf, 0.f) + l1e;
        float pt1 = fminf(fmaxf(pp,       1e-6f), 1.f - 1e-6f);
        float pt0 = fminf(fmaxf(1.f - pp, 1e-6f), 1.f - 1e-6f);
        float a1 = 1.f - pt1, a0 = 1.f - pt0;
        fd = 0.25f*a1*a1*ce1 - 0.75f*a0*a0*ce0;
    }
    s_ci[tid] = ci; s_fd[tid] = fd; s_ok[tid] = ok ? 1 : 0;
    __syncthreads();

    if (tid < Bn) {
        float sc = 0.f, sf = 0.f; int n = 0;
        #pragma unroll
        for (int i = 0; i < Mn; i++) {
            sc += s_ci[(tid<<6) + i];
            sf += s_fd[(tid<<6) + i];
            n  += s_ok[(tid<<6) + i];
        }
        float conf_loss = (g_focal[tid] + sf) / (float)Nn;
        float box = (n > 0) ? sc / (float)n : 0.f;
        s_per[tid] = conf_loss + box;
    }
    __syncthreads();
    if (tid == 0) {
        float s = 0.f;
        #pragma unroll
        for (int i = 0; i < Bn; i++) s += s_per[i];
        out[0] = s * (1.f / (float)Bn);
    }
}

extern "C" void kernel_launch(void* const* d_in, const int* in_sizes, int n_in,
                              void* d_out, int out_size) {
    const float* preds   = (const float*)d_in[0];
    const float* targets = (const float*)d_in[1];
    float* out = (float*)d_out;

    k_init <<<4, 256>>>();
    k_main <<<dim3(NTILES, Bn), 256>>>(preds, targets);
    k_final<<<1, Bn*Mn>>>(preds, targets, out);
}

// round 4
// speedup vs baseline: 1.9937x; 1.0019x over previous
#include <cuda_runtime.h>
#include <math.h>

#define Bn 16
#define Nn 25000
#define Mn 64
#define TILE 256
#define NTILES ((Nn + TILE - 1) / TILE)   // 98

// ---- scratch (no allocations allowed; zero-initialized at load) ----
// g_pack is maintained by atomicMax (idempotent across graph replays) and
// reset to 0 by k_final each call. g_focal likewise reset by k_final.
__device__ unsigned long long g_pack[Bn*Mn];   // (iou_bits<<32) | ~idx
__device__ float g_focal[Bn];

// One 256-pred tile per block. Lane l of each warp owns targets l and l+32 in
// registers; each warp streams its 32 preds of the tile via broadcast LDS.
// Argmax is fully branchless: packed u64 compare+select.
__global__ __launch_bounds__(256) void k_main(const float* __restrict__ preds,
                                              const float* __restrict__ targets) {
    const int b    = blockIdx.y;
    const int base = blockIdx.x * TILE;
    const int tid  = threadIdx.x;
    const int lane = tid & 31;
    const int warp = tid >> 5;

    __shared__ float4 s_box[TILE];
    __shared__ float  s_area[TILE];
    __shared__ unsigned long long s_m[8*Mn];
    __shared__ float  s_red[8];

    const float4 t0 = __ldg((const float4*)targets + (b*Mn + lane));
    const float4 t1 = __ldg((const float4*)targets + (b*Mn + lane + 32));
    const float ta0 = (t0.z - t0.x) * (t0.w - t0.y);
    const float ta1 = (t1.z - t1.x) * (t1.w - t1.y);

    const int cnt = min(TILE, Nn - base);
    float facc = 0.f;
    {
        // stage + convert + focal(target=0): one pred per thread
        float x1, y1, x2, y2, area;
        if (tid < cnt) {
            const float* pr = preds + ((size_t)b * Nn + base + tid) * 5;
            float cx = pr[0], cy = pr[1];
            float w = fmaxf(pr[2], 1e-4f), h = fmaxf(pr[3], 1e-4f);
            float conf = pr[4];
            x1 = cx - 0.5f * w; x2 = cx + 0.5f * w;
            y1 = cy - 0.5f * h; y2 = cy + 0.5f * h;
            area = (x2 - x1) * (y2 - y1);
            float p  = 1.f / (1.f + expf(-conf));
            float ce = fmaxf(conf, 0.f) + log1pf(expf(-fabsf(conf)));
            float pt = fminf(fmaxf(1.f - p, 1e-6f), 1.f - 1e-6f);
            float om = 1.f - pt;
            facc = 0.75f * om * om * ce;
        } else {
            // pad: degenerate far box -> iou exactly 0; its cid > all real
            // cids, so ~cid loses every tie against real candidates.
            x1 = y1 = x2 = y2 = -3e8f; area = 0.f;
        }
        s_box[tid]  = make_float4(x1, y1, x2, y2);
        s_area[tid] = area;
    }
    __syncthreads();

    // iou >= 0 always (areas > 0 after clamping), so float bits are
    // monotone as unsigned. Pack value in hi 32, ~idx in lo 32.
    unsigned long long best0 = 0ull, best1 = 0ull;
    const unsigned npb = ~(unsigned)(base + warp * 32);   // ~pbase

    #pragma unroll
    for (int k = 0; k < 32; k++) {
        const float4 bx = s_box[warp * 32 + k];   // broadcast LDS
        const float  ar = s_area[warp * 32 + k];
        const unsigned lo = npb - (unsigned)k;    // == ~(pbase + k)
        {
            float iw = fmaxf(fminf(bx.z, t0.z) - fmaxf(bx.x, t0.x), 0.f);
            float ih = fmaxf(fminf(bx.w, t0.w) - fmaxf(bx.y, t0.y), 0.f);
            float inter = iw * ih;
            float iou = __fdividef(inter, ar + ta0 - inter);
            unsigned long long c =
                ((unsigned long long)__float_as_uint(iou) << 32) | lo;
            best0 = (c > best0) ? c : best0;
        }
        {
            float iw = fmaxf(fminf(bx.z, t1.z) - fmaxf(bx.x, t1.x), 0.f);
            float ih = fmaxf(fminf(bx.w, t1.w) - fmaxf(bx.y, t1.y), 0.f);
            float inter = iw * ih;
            float iou = __fdividef(inter, ar + ta1 - inter);
            unsigned long long c =
                ((unsigned long long)__float_as_uint(iou) << 32) | lo;
            best1 = (c > best1) ? c : best1;
        }
    }

    s_m[warp*Mn + lane]      = best0;
    s_m[warp*Mn + lane + 32] = best1;

    // focal warp-reduce
    #pragma unroll
    for (int off = 16; off; off >>= 1)
        facc += __shfl_xor_sync(0xffffffffu, facc, off);
    if (lane == 0) s_red[warp] = facc;
    __syncthreads();

    if (tid < Mn) {
        unsigned long long bv = 0ull;
        #pragma unroll
        for (int w = 0; w < 8; w++) {
            unsigned long long v = s_m[w*Mn + tid];
            bv = (v > bv) ? v : bv;
        }
        atomicMax(&g_pack[b*Mn + tid], bv);
    }
    if (tid == 64) {
        float s = 0.f;
        #pragma unroll
        for (int w = 0; w < 8; w++) s += s_red[w];
        atomicAdd(&g_focal[b], s);
    }
}

// Single block: greedy dedup (closed form), CIoU, focal corrections, final
// mean, then reset scratch for the next graph replay.
__global__ __launch_bounds__(1024) void k_final(const float* __restrict__ preds,
                                                const float* __restrict__ targets,
                                                float* __restrict__ out) {
    const int tid = threadIdx.x;          // tid = b*64 + m
    const int b = tid >> 6, m = tid & 63;

    __shared__ float s_iou[Bn*Mn];
    __shared__ int   s_idx[Bn*Mn];
    __shared__ float s_ci[Bn*Mn], s_fd[Bn*Mn];
    __shared__ unsigned char s_ok[Bn*Mn];
    __shared__ float s_per[Bn];

    unsigned long long v = g_pack[tid];
    g_pack[tid] = 0ull;                    // reset for next replay (same thread)
    float iou_b = __uint_as_float((unsigned)(v >> 32));
    int   idx   = (int)(~(unsigned)v);
    s_iou[tid] = iou_b;
    s_idx[tid] = idx;
    __syncthreads();

    bool ok = iou_b > 0.2f;
    if (ok) {
        for (int mp = 0; mp < m; mp++)
            if (s_idx[(b<<6) + mp] == idx && s_iou[(b<<6) + mp] > 0.2f) { ok = false; break; }
    }

    float ci = 0.f, fd = 0.f;
    if (ok) {
        const float* pr = preds + ((size_t)b*Nn + idx) * 5;
        float cx = pr[0], cy = pr[1];
        float w = fmaxf(pr[2], 1e-4f), h = fmaxf(pr[3], 1e-4f);
        float conf = pr[4];
        float x1p = cx - 0.5f*w, x2p = cx + 0.5f*w;
        float y1p = cy - 0.5f*h, y2p = cy + 0.5f*h;
        float4 t = __ldg((const float4*)targets + tid);
        float x1t = t.x, y1t = t.y, x2t = t.z, y2t = t.w;

        float inter = fmaxf(fminf(x2p,x2t) - fmaxf(x1p,x1t), 0.f)
                    * fmaxf(fminf(y2p,y2t) - fmaxf(y1p,y1t), 0.f);
        float un  = (x2p-x1p)*(y2p-y1p) + (x2t-x1t)*(y2t-y1t) - inter;
        float iou = inter / (un + 1e-7f);
        float cw = fmaxf(x2p,x2t) - fminf(x1p,x1t);
        float ch = fmaxf(y2p,y2t) - fminf(y1p,y1t);
        float diag = cw*cw + ch*ch + 1e-7f;
        float dx = x1p + x2p - x1t - x2t;
        float dy = y1p + y2p - y1t - y2t;
        float centers = (dx*dx + dy*dy) * 0.25f;
        float wp = x2p - x1p, hp = y2p - y1p;
        float wt = x2t - x1t, ht = y2t - y1t;
        float dv = atanf(wt/ht) - atanf(wp/hp);
        float vv = (float)(4.0/(M_PI*M_PI)) * dv * dv;
        float alpha = vv / (1.f - iou + vv + 1e-7f);
        ci = 1.f - iou + centers/diag + alpha*vv;

        // focal(target=1) - focal(target=0) correction for this pred
        float pp  = 1.f / (1.f + expf(-conf));
        float l1e = log1pf(expf(-fabsf(conf)));
        float ce1 = fmaxf(conf, 0.f) - conf + l1e;
        float ce0 = fmaxf(conf, 0.f) + l1e;
        float pt1 = fminf(fmaxf(pp,       1e-6f), 1.f - 1e-6f);
        float pt0 = fminf(fmaxf(1.f - pp, 1e-6f), 1.f - 1e-6f);
        float a1 = 1.f - pt1, a0 = 1.f - pt0;
        fd = 0.25f*a1*a1*ce1 - 0.75f*a0*a0*ce0;
    }
    s_ci[tid] = ci; s_fd[tid] = fd; s_ok[tid] = ok ? 1 : 0;
    __syncthreads();

    if (tid < Bn) {
        float sc = 0.f, sf = 0.f; int n = 0;
        #pragma unroll
        for (int i = 0; i < Mn; i++) {
            sc += s_ci[(tid<<6) + i];
            sf += s_fd[(tid<<6) + i];
            n  += s_ok[(tid<<6) + i];
        }
        float conf_loss = (g_focal[tid] + sf) / (float)Nn;
        g_focal[tid] = 0.f;                // reset for next replay
        float box = (n > 0) ? sc / (float)n : 0.f;
        s_per[tid] = conf_loss + box;
    }
    __syncthreads();
    if (tid == 0) {
        float s = 0.f;
        #pragma unroll
        for (int i = 0; i < Bn; i++) s += s_per[i];
        out[0] = s * (1.f / (float)Bn);
    }
}

extern "C" void kernel_launch(void* const* d_in, const int* in_sizes, int n_in,
                              void* d_out, int out_size) {
    const float* preds   = (const float*)d_in[0];
    const float* targets = (const float*)d_in[1];
    float* out = (float*)d_out;

    k_main <<<dim3(NTILES, Bn), 256>>>(preds, targets);
    k_final<<<1, Bn*Mn>>>(preds, targets, out);
}

// round 5
// speedup vs baseline: 2.6518x; 1.3301x over previous
#include <cuda_runtime.h>
#include <math.h>

#define Bn 16
#define Nn 25000
#define Mn 64
#define TILE 256
#define NTILES ((Nn + TILE - 1) / TILE)   // 98

// ---- scratch (no allocations allowed; zero-initialized at load) ----
// g_pack maintained by atomicMax (idempotent across replays), reset by k_final.
__device__ unsigned long long g_pack[Bn*Mn];   // (iou_bits<<32) | ~idx
__device__ float g_focal[Bn];

__global__ void k_zero(float* out) { if (threadIdx.x == 0) out[0] = 0.f; }
__global__ void k_nop() {}

// One 256-pred tile per block. Lane l of each warp owns targets l and l+32 in
// registers; each warp streams its 32 preds of the tile via broadcast LDS.
// Running argmax is scalar branchless: FSETP + SEL pairs.
__global__ __launch_bounds__(256) void k_main(const float* __restrict__ preds,
                                              const float* __restrict__ targets) {
    const int b    = blockIdx.y;
    const int base = blockIdx.x * TILE;
    const int tid  = threadIdx.x;
    const int lane = tid & 31;
    const int warp = tid >> 5;

    __shared__ float4 s_box[TILE];
    __shared__ float  s_area[TILE];
    __shared__ unsigned long long s_m[8*Mn];
    __shared__ float  s_red[8];

    const float4 t0 = __ldg((const float4*)targets + (b*Mn + lane));
    const float4 t1 = __ldg((const float4*)targets + (b*Mn + lane + 32));
    const float ta0 = (t0.z - t0.x) * (t0.w - t0.y);
    const float ta1 = (t1.z - t1.x) * (t1.w - t1.y);

    const int cnt = min(TILE, Nn - base);
    float facc = 0.f;
    {
        // stage + convert + focal(target=0): one pred per thread
        float x1, y1, x2, y2, area;
        if (tid < cnt) {
            const float* pr = preds + ((size_t)b * Nn + base + tid) * 5;
            float cx = pr[0], cy = pr[1];
            float w = fmaxf(pr[2], 1e-4f), h = fmaxf(pr[3], 1e-4f);
            float conf = pr[4];
            x1 = cx - 0.5f * w; x2 = cx + 0.5f * w;
            y1 = cy - 0.5f * h; y2 = cy + 0.5f * h;
            area = (x2 - x1) * (y2 - y1);
            float p  = 1.f / (1.f + expf(-conf));
            float ce = fmaxf(conf, 0.f) + log1pf(expf(-fabsf(conf)));
            float pt = fminf(fmaxf(1.f - p, 1e-6f), 1.f - 1e-6f);
            float om = 1.f - pt;
            facc = 0.75f * om * om * ce;
        } else {
            // pad: degenerate far box -> iou exactly 0; idx > all real cids,
            // so it loses every tie at the pack/merge stage.
            x1 = y1 = x2 = y2 = -3e8f; area = 0.f;
        }
        s_box[tid]  = make_float4(x1, y1, x2, y2);
        s_area[tid] = area;
    }
    __syncthreads();

    // iou >= 0 always; strict > over increasing k keeps the FIRST max,
    // matching argmax semantics within this warp's stream.
    float best0 = -1.f, best1 = -1.f;
    int   bk0 = 0, bk1 = 0;
    const int pbase = base + warp * 32;

    #pragma unroll
    for (int k = 0; k < 32; k++) {
        const float4 bx = s_box[warp * 32 + k];   // broadcast LDS
        const float  ar = s_area[warp * 32 + k];
        {
            float iw = fmaxf(fminf(bx.z, t0.z) - fmaxf(bx.x, t0.x), 0.f);
            float ih = fmaxf(fminf(bx.w, t0.w) - fmaxf(bx.y, t0.y), 0.f);
            float inter = iw * ih;
            float iou = __fdividef(inter, ar + ta0 - inter);
            bool p = iou > best0;
            best0 = p ? iou : best0;
            bk0   = p ? (pbase + k) : bk0;
        }
        {
            float iw = fmaxf(fminf(bx.z, t1.z) - fmaxf(bx.x, t1.x), 0.f);
            float ih = fmaxf(fminf(bx.w, t1.w) - fmaxf(bx.y, t1.y), 0.f);
            float inter = iw * ih;
            float iou = __fdividef(inter, ar + ta1 - inter);
            bool p = iou > best1;
            best1 = p ? iou : best1;
            bk1   = p ? (pbase + k) : bk1;
        }
    }

    // pack once: higher iou wins; on tie, ~idx makes SMALLER idx win
    s_m[warp*Mn + lane] =
        ((unsigned long long)__float_as_uint(best0) << 32) | (unsigned)(~bk0);
    s_m[warp*Mn + lane + 32] =
        ((unsigned long long)__float_as_uint(best1) << 32) | (unsigned)(~bk1);

    // focal warp-reduce
    #pragma unroll
    for (int off = 16; off; off >>= 1)
        facc += __shfl_xor_sync(0xffffffffu, facc, off);
    if (lane == 0) s_red[warp] = facc;
    __syncthreads();

    if (tid < Mn) {
        unsigned long long bv = 0ull;
        #pragma unroll
        for (int w = 0; w < 8; w++) {
            unsigned long long v = s_m[w*Mn + tid];
            bv = (v > bv) ? v : bv;
        }
        atomicMax(&g_pack[b*Mn + tid], bv);
    }
    if (tid == 64) {
        float s = 0.f;
        #pragma unroll
        for (int w = 0; w < 8; w++) s += s_red[w];
        atomicAdd(&g_focal[b], s);
    }
}

// One image per block (16 blocks x 64 threads): greedy dedup (closed form),
// CIoU, focal corrections, per-image loss, atomicAdd of mean contribution.
// Also resets scratch for the next graph replay.
__global__ __launch_bounds__(64) void k_final(const float* __restrict__ preds,
                                              const float* __restrict__ targets,
                                              float* __restrict__ out) {
    const int b = blockIdx.x;
    const int m = threadIdx.x;

    __shared__ float s_iou[Mn];
    __shared__ int   s_idx[Mn];
    __shared__ float s_ci[Mn], s_fd[Mn];
    __shared__ unsigned char s_ok[Mn];

    unsigned long long v = g_pack[b*Mn + m];
    g_pack[b*Mn + m] = 0ull;               // reset for next replay
    float iou_b = __uint_as_float((unsigned)(v >> 32));
    int   idx   = (int)(~(unsigned)v);
    s_iou[m] = iou_b;
    s_idx[m] = idx;
    __syncthreads();

    bool ok = iou_b > 0.2f;
    if (ok) {
        for (int mp = 0; mp < m; mp++)
            if (s_idx[mp] == idx && s_iou[mp] > 0.2f) { ok = false; break; }
    }

    float ci = 0.f, fd = 0.f;
    if (ok) {
        const float* pr = preds + ((size_t)b*Nn + idx) * 5;
        float cx = pr[0], cy = pr[1];
        float w = fmaxf(pr[2], 1e-4f), h = fmaxf(pr[3], 1e-4f);
        float conf = pr[4];
        float x1p = cx - 0.5f*w, x2p = cx + 0.5f*w;
        float y1p = cy - 0.5f*h, y2p = cy + 0.5f*h;
        float4 t = __ldg((const float4*)targets + (b*Mn + m));
        float x1t = t.x, y1t = t.y, x2t = t.z, y2t = t.w;

        float inter = fmaxf(fminf(x2p,x2t) - fmaxf(x1p,x1t), 0.f)
                    * fmaxf(fminf(y2p,y2t) - fmaxf(y1p,y1t), 0.f);
        float un  = (x2p-x1p)*(y2p-y1p) + (x2t-x1t)*(y2t-y1t) - inter;
        float iou = inter / (un + 1e-7f);
        float cw = fmaxf(x2p,x2t) - fminf(x1p,x1t);
        float ch = fmaxf(y2p,y2t) - fminf(y1p,y1t);
        float diag = cw*cw + ch*ch + 1e-7f;
        float dx = x1p + x2p - x1t - x2t;
        float dy = y1p + y2p - y1t - y2t;
        float centers = (dx*dx + dy*dy) * 0.25f;
        float wp = x2p - x1p, hp = y2p - y1p;
        float wt = x2t - x1t, ht = y2t - y1t;
        float dv = atanf(wt/ht) - atanf(wp/hp);
        float vv = (float)(4.0/(M_PI*M_PI)) * dv * dv;
        float alpha = vv / (1.f - iou + vv + 1e-7f);
        ci = 1.f - iou + centers/diag + alpha*vv;

        // focal(target=1) - focal(target=0) correction for this pred
        float pp  = 1.f / (1.f + expf(-conf));
        float l1e = log1pf(expf(-fabsf(conf)));
        float ce1 = fmaxf(conf, 0.f) - conf + l1e;
        float ce0 = fmaxf(conf, 0.f) + l1e;
        float pt1 = fminf(fmaxf(pp,       1e-6f), 1.f - 1e-6f);
        float pt0 = fminf(fmaxf(1.f - pp, 1e-6f), 1.f - 1e-6f);
        float a1 = 1.f - pt1, a0 = 1.f - pt0;
        fd = 0.25f*a1*a1*ce1 - 0.75f*a0*a0*ce0;
    }
    s_ci[m] = ci; s_fd[m] = fd; s_ok[m] = ok ? 1 : 0;
    __syncthreads();

    if (m == 0) {
        float sc = 0.f, sf = 0.f; int n = 0;
        #pragma unroll
        for (int i = 0; i < Mn; i++) {
            sc += s_ci[i]; sf += s_fd[i]; n += s_ok[i];
        }
        float conf_loss = (g_focal[b] + sf) / (float)Nn;
        g_focal[b] = 0.f;                  // reset for next replay
        float box = (n > 0) ? sc / (float)n : 0.f;
        atomicAdd(out, (conf_loss + box) * (1.f / (float)Bn));
    }
}

extern "C" void kernel_launch(void* const* d_in, const int* in_sizes, int n_in,
                              void* d_out, int out_size) {
    const float* preds   = (const float*)d_in[0];
    const float* targets = (const float*)d_in[1];
    float* out = (float*)d_out;

    // Order chosen so k_main is global launch #6 -> ncu (-s 5 -c 1) profiles it.
    k_zero <<<1, 32>>>(out);
    k_nop  <<<1, 32>>>();
    k_nop  <<<1, 32>>>();
    k_main <<<dim3(NTILES, Bn), 256>>>(preds, targets);
    k_final<<<Bn, Mn>>>(preds, targets, out);
}